// round 1
// baseline (speedup 1.0000x reference)
#include <cuda_runtime.h>
#include <cuda_bf16.h>

// OntologyNN: K=8-ary complete tree, DEPTH=5.
// NUM_NODES = 37449, leaves = nodes [4681, 37449), level-4 parents = [585, 4681),
// level-3 = [73, 585), level-2 = [9, 73), level-1 = [1, 9), root = 0.
// out[b][p] = clamp(sum_k sigmoid(w[8p+1+k]) * val(8p+1+k), 0, 1) for internal p,
// out[b][leaf] = in[b][leaf].

#define NODES      37449
#define BATCHN     2048
#define LEAF_START 4681
#define NUM_LEAVES 32768
#define L4_START   585
#define TPB        256

// Precomputed sigmoid(weights). Static device global (no allocation).
__device__ float g_sw[NODES];

__global__ void sigmoid_kernel(const float* __restrict__ w) {
    int i = blockIdx.x * blockDim.x + threadIdx.x;
    if (i < NODES) {
        float x = w[i];
        g_sw[i] = 1.0f / (1.0f + expf(-x));
    }
}

__global__ void __launch_bounds__(TPB) tree_kernel(const float* __restrict__ in,
                                                   float* __restrict__ out) {
    // Internal node values for this batch row: nodes 0..4680 (18724 B).
    __shared__ float internal[LEAF_START];

    const long long row = (long long)blockIdx.x * NODES;
    const float* __restrict__ inr  = in  + row;
    float*       __restrict__ outr = out + row;
    const int tid  = threadIdx.x;
    const int lane = tid & 7;

    // ---- Phase 1: stream leaves (copy to out) + compute level-4 parents ----
    // Lane-contiguous scalar accesses: warp covers a contiguous 128B chunk per
    // instruction (row base is only 4B aligned, so no vector loads). Each
    // 8-lane group reduces to one parent via shfl_xor.
    #pragma unroll 4
    for (int e = tid; e < NUM_LEAVES; e += TPB) {
        const int node = LEAF_START + e;
        float v  = __ldg(inr + node);
        float sw = g_sw[node];
        outr[node] = v;                       // leaf pass-through
        float prod = v * sw;
        prod += __shfl_xor_sync(0xffffffffu, prod, 1);
        prod += __shfl_xor_sync(0xffffffffu, prod, 2);
        prod += __shfl_xor_sync(0xffffffffu, prod, 4);
        if (lane == 0) {
            const int p = L4_START + (e >> 3);
            float r = fminf(fmaxf(prod, 0.0f), 1.0f);
            internal[p] = r;
            outr[p] = r;
        }
    }
    __syncthreads();

    // ---- Phases 2..5: upper levels from shared memory ----
    // level 3: 512 parents [73,585)
    for (int j = tid; j < 512; j += TPB) {
        const int p = 73 + j;
        const int c = 8 * p + 1;
        float s = 0.0f;
        #pragma unroll
        for (int k = 0; k < 8; ++k) s += internal[c + k] * g_sw[c + k];
        float r = fminf(fmaxf(s, 0.0f), 1.0f);
        internal[p] = r;
        outr[p] = r;
    }
    __syncthreads();

    // level 2: 64 parents [9,73)
    if (tid < 64) {
        const int p = 9 + tid;
        const int c = 8 * p + 1;
        float s = 0.0f;
        #pragma unroll
        for (int k = 0; k < 8; ++k) s += internal[c + k] * g_sw[c + k];
        float r = fminf(fmaxf(s, 0.0f), 1.0f);
        internal[p] = r;
        outr[p] = r;
    }
    __syncthreads();

    // level 1: 8 parents [1,9)
    if (tid < 8) {
        const int p = 1 + tid;
        const int c = 8 * p + 1;
        float s = 0.0f;
        #pragma unroll
        for (int k = 0; k < 8; ++k) s += internal[c + k] * g_sw[c + k];
        float r = fminf(fmaxf(s, 0.0f), 1.0f);
        internal[p] = r;
        outr[p] = r;
    }
    __syncthreads();

    // root: node 0
    if (tid == 0) {
        float s = 0.0f;
        #pragma unroll
        for (int k = 1; k <= 8; ++k) s += internal[k] * g_sw[k];
        outr[0] = fminf(fmaxf(s, 0.0f), 1.0f);
    }
}

extern "C" void kernel_launch(void* const* d_in, const int* in_sizes, int n_in,
                              void* d_out, int out_size) {
    const float* probs = (const float*)d_in[0];   // [2048, 37449] fp32
    const float* w     = (const float*)d_in[1];   // [37449] fp32
    float* out = (float*)d_out;                   // [2048, 37449] fp32

    sigmoid_kernel<<<(NODES + TPB - 1) / TPB, TPB>>>(w);
    tree_kernel<<<BATCHN, TPB>>>(probs, out);
}

// round 2
// speedup vs baseline: 1.5217x; 1.5217x over previous
#include <cuda_runtime.h>
#include <cuda_bf16.h>

// OntologyNN: K=8 complete tree, DEPTH=5. NUM_NODES=37449.
// leaves = nodes [4681,37449) (32768), L4 parents [585,4681), L3 [73,585),
// L2 [9,73), L1 [1,9), root 0.
// out[b][p] = clamp(sum_k sigmoid(w[8p+1+k]) * val(8p+1+k), 0, 1); leaves pass through.

#define NODES      37449
#define BATCHN     2048
#define LEAF_START 4681
#define L4_START   585
#define TPB        256
#define NWARP      8
#define SWSTRIDE   37460   // NODES+11 rounded to multiple of 4 (keeps each copy 16B-aligned)

// 4 shifted copies of sigmoid(w): g_sw4[c][j] = sigmoid(w[j+c]).
// Lets any row alignment do aligned float4 loads of the weights.
__device__ __align__(16) float g_sw4[4][SWSTRIDE];

__global__ void sigmoid_kernel(const float* __restrict__ w) {
    int i = blockIdx.x * blockDim.x + threadIdx.x;
    if (i < NODES + 8) {
        float s = 0.0f;
        if (i < NODES) s = 1.0f / (1.0f + expf(-w[i]));
        #pragma unroll
        for (int c = 0; c < 4; ++c) {
            int j = i - c;
            if (j >= 0) g_sw4[c][j] = s;
        }
    }
}

__device__ __forceinline__ float clamp01(float v) {
    return fminf(fmaxf(v, 0.0f), 1.0f);
}

__global__ void __launch_bounds__(TPB) tree_kernel(const float* __restrict__ in,
                                                   float* __restrict__ out) {
    __shared__ float internal[LEAF_START];   // nodes 0..4680 for this row

    const int b   = blockIdx.x;
    const long long row = (long long)b * NODES;
    const float* __restrict__ inr  = in  + row;
    float*       __restrict__ outr = out + row;
    const int tid  = threadIdx.x;
    const int lane = tid & 31;
    const int wid  = tid >> 5;

    // Element-index misalignment of the leaf base within a 16B chunk:
    // (37449*b + 4681) mod 4 == (b+1) mod 4
    const int a = (b + 1) & 3;
    // Shift copy index so weight vectors are 16B aligned: c == (1 - a) mod 4
    const int c = (4 - (b & 3)) & 3;
    const float* __restrict__ swp = g_sw4[c];
    const unsigned F = 0xffffffffu;

    // ---- Phase 1: one warp per 256-leaf window; fully vectorized stream. ----
    // Window w covers leaves [W, W+256). Cover region [W-a, W+260) is 16B-aligned.
    // Groups of 8 leaves (absolute, 8-aligned) -> L4 parents 585 + 32w + g.
    for (int w = wid; w < 128; w += NWARP) {
        const int W  = w << 8;
        const int ex = LEAF_START + W - a;           // row-relative idx of cover start (aligned)
        const float4* inx = (const float4*)(inr + ex);
        float4 x = inx[lane];                        // leaves W-a+4*lane   .. +3
        float4 y = inx[32 + lane];                   // leaves W-a+128+4*lane .. +3

        const int n0 = ex + 4 * lane;                // node index of x.x
        const float4* swx = (const float4*)(swp + (n0 - c));
        float4 wx = swx[0];
        float4 wy = swx[32];

        // Leaf pass-through (same addresses in out -> aligned STG.128).
        // Head overlap into L4 region is benign (overwritten after syncthreads);
        // interior window overlaps rewrite identical values.
        float4* outx = (float4*)(outr + ex);
        outx[lane]      = x;
        outx[32 + lane] = y;

        float tX, tY;
        if (a == 0) {
            // Perfectly aligned: lane pairs form the groups directly.
            float sx = x.x*wx.x + x.y*wx.y + x.z*wx.z + x.w*wx.w;
            float sy = y.x*wy.x + y.y*wy.y + y.z*wy.z + y.w*wy.w;
            tX = sx + __shfl_down_sync(F, sx, 1);
            tY = sy + __shfl_down_sync(F, sy, 1);
        } else {
            // Extra float4 'z' (lane 0): duplicates next window's head; completes group 31.
            float4 z  = make_float4(0.f, 0.f, 0.f, 0.f);
            float4 wz = make_float4(0.f, 0.f, 0.f, 0.f);
            if (lane == 0) {
                const int nz = ex + 256;             // aligned, row-relative
                wz = *(const float4*)(swp + (nz - c));
                if (b == BATCHN - 1 && w == 127) {
                    // last row, last window: full float4 would read past the buffer
                    float* zp = (float*)&z;
                    #pragma unroll
                    for (int i = 0; i < 3; ++i)
                        if (i < a) zp[i] = inr[nz + i];
                } else {
                    z = *(const float4*)(inr + nz);
                }
                if (w == 127) {
                    // tail leaves [32768-a, 32768) are only covered by z
                    float* zp = (float*)&z;
                    #pragma unroll
                    for (int i = 0; i < 3; ++i)
                        if (i < a) outr[nz + i] = zp[i];
                }
            }

            float px0 = x.x*wx.x, px1 = x.y*wx.y, px2 = x.z*wx.z, px3 = x.w*wx.w;
            float py0 = y.x*wy.x, py1 = y.y*wy.y, py2 = y.z*wy.z, py3 = y.w*wy.w;

            // Split each lane's 4 products at the 8-group boundary:
            // even lanes split at i=a; odd lanes are whole (ib=4).
            const int ib = (lane & 1) ? 4 : a;
            float loX = px0;
            if (ib > 1) loX += px1;
            if (ib > 2) loX += px2;
            if (ib > 3) loX += px3;
            float hiX = ((px0 + px1) + (px2 + px3)) - loX;
            float loY = py0;
            if (ib > 1) loY += py1;
            if (ib > 2) loY += py2;
            if (ib > 3) loY += py3;
            float hiY = ((py0 + py1) + (py2 + py3)) - loY;

            float zLo = 0.0f;
            if (lane == 0) {
                float* zp = (float*)&z; float* wzp = (float*)&wz;
                #pragma unroll
                for (int i = 0; i < 3; ++i)
                    if (i < a) zLo += zp[i] * wzp[i];
            }
            // group m (even lane 2m): hi(2m) + lo(2m+1) + lo(2m+2)
            float yLo0 = __shfl_sync(F, loY, 0);     // patches x-group 15
            float zLo0 = __shfl_sync(F, zLo, 0);     // patches y-group 15 (abs 31)
            float aX1 = __shfl_down_sync(F, loX, 1);
            float aX2 = __shfl_down_sync(F, loX, 2);
            float aY1 = __shfl_down_sync(F, loY, 1);
            float aY2 = __shfl_down_sync(F, loY, 2);
            if (lane == 30) { aX2 = yLo0; aY2 = zLo0; }
            tX = hiX + aX1 + aX2;
            tY = hiY + aY1 + aY2;
        }

        if (!(lane & 1)) {
            const int m = lane >> 1;                 // 0..15
            const int p = L4_START + (w << 5) + m;   // x-groups; y-groups at +16
            float gx = clamp01(tX);
            float gy = clamp01(tY);
            internal[p]      = gx;
            internal[p + 16] = gy;
            outr[p]      = gx;
            outr[p + 16] = gy;
        }
    }
    __syncthreads();

    // ---- Upper levels from shared memory (unshifted weights = g_sw4[1]-1? use copy 0) ----
    const float* __restrict__ sw0 = g_sw4[0];        // sw0[j] = sigmoid(w[j])

    // level 3: parents [73, 585)
    for (int j = tid; j < 512; j += TPB) {
        const int p = 73 + j, cc = 8 * p + 1;
        float s = 0.0f;
        #pragma unroll
        for (int k = 0; k < 8; ++k) s += internal[cc + k] * sw0[cc + k];
        float r = clamp01(s);
        internal[p] = r;
        outr[p] = r;
    }
    __syncthreads();

    // level 2: parents [9, 73)
    if (tid < 64) {
        const int p = 9 + tid, cc = 8 * p + 1;
        float s = 0.0f;
        #pragma unroll
        for (int k = 0; k < 8; ++k) s += internal[cc + k] * sw0[cc + k];
        float r = clamp01(s);
        internal[p] = r;
        outr[p] = r;
    }
    __syncthreads();

    // level 1: parents [1, 9)
    if (tid < 8) {
        const int p = 1 + tid, cc = 8 * p + 1;
        float s = 0.0f;
        #pragma unroll
        for (int k = 0; k < 8; ++k) s += internal[cc + k] * sw0[cc + k];
        float r = clamp01(s);
        internal[p] = r;
        outr[p] = r;
    }
    __syncthreads();

    // root
    if (tid == 0) {
        float s = 0.0f;
        #pragma unroll
        for (int k = 1; k <= 8; ++k) s += internal[k] * sw0[k];
        outr[0] = clamp01(s);
    }
}

extern "C" void kernel_launch(void* const* d_in, const int* in_sizes, int n_in,
                              void* d_out, int out_size) {
    const float* probs = (const float*)d_in[0];   // [2048, 37449] fp32
    const float* w     = (const float*)d_in[1];   // [37449] fp32
    float* out = (float*)d_out;                   // [2048, 37449] fp32

    sigmoid_kernel<<<(NODES + 8 + TPB - 1) / TPB, TPB>>>(w);
    tree_kernel<<<BATCHN, TPB>>>(probs, out);
}